// round 7
// baseline (speedup 1.0000x reference)
#include <cuda_runtime.h>
#include <cstdint>

// Shapes fixed by setup_inputs: gumbel (4, 1024, 8192)
#define BB 4
#define NN 8192
#define TT 1024
#define C2 1.4426950408889634f   // log2(e)
#define NBLK 147                 // 147*56 >= 8192; all blocks resident (1/SM)
#define NTHR 1024
#define CPB 56
#define PSTR 1025                // padded smem column stride
#define PST 160                  // partial table stride
#define NEG_BIG (-3.402823466e38f)

// Cross-block scratch (device globals; no allocation allowed)
__device__ float g_u[TT];               // u_i = 2^{-6}/S_i (exp domain)
__device__ float g_cmaxb[NBLK];         // per-block local col max (log2)
__device__ float g_part[TT * PST];      // row partials / argmax vals (local scale)
__device__ int   g_pidx[TT * PST];      // argmax indices
__device__ int   g_arr[NBLK];           // barrier arrival epochs (monotonic)

__device__ __forceinline__ float ex2(float x) {
    float r; asm("ex2.approx.ftz.f32 %0, %1;" : "=f"(r) : "f"(x)); return r;
}

// Atomic-free grid barrier: parallel STG arrivals + distributed poll.
// (R5/R6 post-mortem: atomicAdd arrivals to one address serialize in the LTS
// atomic unit at ~3.6us/barrier. STG arrivals are parallel.)
__device__ __forceinline__ void gbar(int base, int& k) {
    k++;
    int target = base + k;
    __syncthreads();
    if (threadIdx.x == 0) {
        __threadfence();
        *(volatile int*)&g_arr[blockIdx.x] = target;
    }
    if (threadIdx.x < 32) {
        bool done;
        do {
            done = true;
#pragma unroll
            for (int q = 0; q < 5; q++) {
                int idx = threadIdx.x + 32 * q;
                if (idx < NBLK && (*(volatile int*)&g_arr[idx] - target) < 0) done = false;
            }
        } while (!__all_sync(0xffffffffu, done));
        __threadfence();
    }
    __syncthreads();
}

__global__ void __launch_bounds__(NTHR, 1)
sinkhorn_persist(const float* __restrict__ g, float* __restrict__ out) {
    extern __shared__ float sm[];
    float* p     = sm;                 // [CPB][PSTR] exp-domain tile (col-major)
    float* ust   = sm + CPB * PSTR;    // [512] staged u half-chunk
    float* c_arr = ust + 512;          // [CPB]
    float* w_s   = c_arr + CPB;        // [CPB] (16B aligned)
    float* misc  = w_s + CPB;          // [0]=Cm_glob, [1]=cmax_local

    int blk = blockIdx.x, tid = threadIdx.x;
    int lw = tid >> 5, l = tid & 31;
    int colbase = blk * CPB;
    int ncols = NN - colbase; if (ncols > CPB) ncols = CPB;

    int base = 0, bk = 0;
    if (tid < 32) base = *(volatile int*)&g_arr[blk];   // epoch snapshot (replay-safe)

    for (int b = 0; b < BB; b++) {
        // ---- build p = 2^(g*C2): warp per row, float2 lanes (coalesced)
        for (int r = lw; r < TT; r += 32) {
            int j = 2 * l;
            if (j < ncols) {
                float2 v = *(const float2*)(g + ((size_t)(b * TT + r)) * NN + colbase + j);
                p[j * PSTR + r]       = ex2(v.x * C2);
                p[(j + 1) * PSTR + r] = ex2(v.y * C2);
            }
        }
        __syncthreads();

        float R0 = 0.0f;
        for (int it = 0; it < 8; it++) {
            // ---- col sweep: S_cj = sum_i p[j][i]*u_i ; warp lw -> cols lw, lw+32
            int j0 = lw, j1 = lw + 32;
            bool v0 = (j0 < ncols), v1 = (j1 < ncols);
            float acc0 = 0.0f, acc1 = 0.0f;
            if (it == 0) {          // u == 1
#pragma unroll
                for (int k = 0; k < 32; k++) {
                    int rr = 32 * k + l;
                    if (v0) acc0 += p[j0 * PSTR + rr];
                    if (v1) acc1 += p[j1 * PSTR + rr];
                }
            } else {
#pragma unroll
                for (int c = 0; c < 2; c++) {
                    if (tid < 512) ust[tid] = __ldcg(&g_u[512 * c + tid]);
                    __syncthreads();
#pragma unroll
                    for (int k = 0; k < 16; k++) {
                        int rr = 32 * k + l;
                        float uu = ust[rr];
                        if (v0) acc0 = fmaf(p[j0 * PSTR + 512 * c + rr], uu, acc0);
                        if (v1) acc1 = fmaf(p[j1 * PSTR + 512 * c + rr], uu, acc1);
                    }
                    __syncthreads();
                }
            }
#pragma unroll
            for (int o = 16; o; o >>= 1) {
                acc0 += __shfl_xor_sync(~0u, acc0, o);
                acc1 += __shfl_xor_sync(~0u, acc1, o);
            }
            if (l == 0) {
                if (v0) c_arr[j0] = -(R0 + __log2f(acc0));
                if (v1) c_arr[j1] = -(R0 + __log2f(acc1));
            }
            __syncthreads();
            // local cmax only (no global exchange here)
            if (lw == 0) {
                float m0 = (l < ncols) ? c_arr[l] : NEG_BIG;
                float m1 = (l + 32 < ncols) ? c_arr[l + 32] : NEG_BIG;
                float m = fmaxf(m0, m1);
#pragma unroll
                for (int o = 16; o; o >>= 1) m = fmaxf(m, __shfl_xor_sync(~0u, m, o));
                if (l == 0) { g_cmaxb[blk] = m; misc[1] = m; }
            }
            __syncthreads();
            float cml = misc[1];
            if (tid < ncols) w_s[tid] = ex2(c_arr[tid] - cml);   // local scale, <=1
            __syncthreads();

            if (it < 7) {
                // ---- row sweep (local scale): thread tid = row
                float s0 = 0.0f, s1 = 0.0f;
                int nj4 = ncols >> 2;
                for (int j4 = 0; j4 < nj4; j4++) {
                    float4 w4 = *(const float4*)&w_s[4 * j4];
                    s0 = fmaf(p[(4 * j4 + 0) * PSTR + tid], w4.x, s0);
                    s1 = fmaf(p[(4 * j4 + 1) * PSTR + tid], w4.y, s1);
                    s0 = fmaf(p[(4 * j4 + 2) * PSTR + tid], w4.z, s0);
                    s1 = fmaf(p[(4 * j4 + 3) * PSTR + tid], w4.w, s1);
                }
                g_part[tid * PST + blk] = s0 + s1;
            } else {
                // ---- argmax over own cols (local scale; rescaled by owner)
                float best = -1.0f; int bidx = 0x7fffffff;
                for (int j = 0; j < ncols; j++) {
                    float v = p[j * PSTR + tid] * w_s[j];
                    if (v > best) { best = v; bidx = colbase + j; }
                }
                g_part[tid * PST + blk] = best;
                g_pidx[tid * PST + blk] = bidx;
            }
            gbar(base, bk);                                   // B_A

            // every block computes identical global Cm (deterministic reduce)
            if (lw == 0) {
                float m = NEG_BIG;
#pragma unroll
                for (int q = 0; q < 5; q++) {
                    int idx = l + 32 * q;
                    if (idx < NBLK) m = fmaxf(m, __ldcg(&g_cmaxb[idx]));
                }
#pragma unroll
                for (int o = 16; o; o >>= 1) m = fmaxf(m, __shfl_xor_sync(~0u, m, o));
                if (l == 0) misc[0] = m;
            }
            __syncthreads();
            float Cm = misc[0];

            if (it < 7) {
                // owners reduce rescaled partials -> u_i = 2^{-6}/S_i
                if (lw < 7) {
                    int i = blk * 7 + lw;
                    if (i < TT) {
                        float s = 0.0f;
#pragma unroll
                        for (int q = 0; q < 5; q++) {
                            int idx = l + 32 * q;
                            if (idx < NBLK) {
                                float f = ex2(__ldcg(&g_cmaxb[idx]) - Cm);
                                s = fmaf(__ldcg(&g_part[i * PST + idx]), f, s);
                            }
                        }
#pragma unroll
                        for (int o = 16; o; o >>= 1) s += __shfl_xor_sync(~0u, s, o);
                        if (l == 0) g_u[i] = 0.015625f / s;
                    }
                }
                R0 = 6.0f - Cm;    // rmax <= 5.53 - Cm (g >= -5.53 bits)
                gbar(base, bk);                               // B_B (u visible)
            } else {
                // owners: cross-block argmax with rescale to common Cm scale
                if (lw < 7) {
                    int i = blk * 7 + lw;
                    if (i < TT) {
                        float bv = -1.0f; int bi = 0x7fffffff;
#pragma unroll
                        for (int q = 0; q < 5; q++) {
                            int idx = l + 32 * q;
                            if (idx < NBLK) {
                                float f = ex2(__ldcg(&g_cmaxb[idx]) - Cm);
                                float v = __ldcg(&g_part[i * PST + idx]) * f;
                                int  id = __ldcg(&g_pidx[i * PST + idx]);
                                if (v > bv || (v == bv && id < bi)) { bv = v; bi = id; }
                            }
                        }
#pragma unroll
                        for (int o = 16; o; o >>= 1) {
                            float v = __shfl_xor_sync(~0u, bv, o);
                            int  id = __shfl_xor_sync(~0u, bi, o);
                            if (v > bv || (v == bv && id < bi)) { bv = v; bi = id; }
                        }
                        if (l == 0) {
                            out[b * TT + i] = 1.0f;             // s + stopgrad(1-s) == 1.0
                            out[BB * TT + b * TT + i] = (float)bi;
                        }
                    }
                }
                gbar(base, bk);   // B_B: protect g_part/g_cmaxb before next batch
            }
        } // it
    } // b
}

extern "C" void kernel_launch(void* const* d_in, const int* in_sizes, int n_in,
                              void* d_out, int out_size) {
    // x and routing_token are mathematically dead: scores cancel in the first
    // axis=-2 normalization. Only gumbel matters.
    const float* g = (const float*)d_in[2];
    float* out = (float*)d_out;

    const int smem = (CPB * PSTR + 512 + CPB + CPB + 8) * 4;  // 232,128 B
    static bool attr_set = false;
    if (!attr_set) {
        cudaFuncSetAttribute(sinkhorn_persist,
                             cudaFuncAttributeMaxDynamicSharedMemorySize, smem);
        attr_set = true;
    }
    sinkhorn_persist<<<NBLK, NTHR, smem>>>(g, out);
}

// round 8
// speedup vs baseline: 2.5021x; 2.5021x over previous
#include <cuda_runtime.h>
#include <cstdint>

// Shapes fixed by setup_inputs: gumbel (4, 1024, 8192)
#define BB 4
#define NN 8192
#define TT 1024
#define C2 1.4426950408889634f     // log2(e): all work in base-2 log domain
#define GB2 66.6f                  // safe offset bits (gumbel <= 46.05 nats)
#define NEG_BIG (-3.402823466e38f)

// Scratch (device globals; no allocation allowed)
__device__ float g_r[BB * TT];     // row offsets r_i (log2 domain)
__device__ float g_v[BB * NN];     // col offsets c_j (log2 domain)

__device__ __forceinline__ float ex2(float x) {
    float r; asm("ex2.approx.ftz.f32 %0, %1;" : "=f"(r) : "f"(x)); return r;
}

__global__ void k_init() {
    int i = blockIdx.x * blockDim.x + threadIdx.x;
    if (i < BB * TT) g_r[i] = 0.0f;
}

// ---- col pass (proven R3 version): c_j = -(Mc + log2 sum_i 2^(g*C2 + r_i - Mc))
// block: 512 thr = 32 cols x 16 chunks x 64 rows. grid: 2 batches * 256 tiles.
__global__ void __launch_bounds__(512) k_col(const float* __restrict__ g, int b0) {
    __shared__ float rr[TT];        // r - Mc
    __shared__ float red[17];
    __shared__ float ps[16][32];
    int tid = threadIdx.x;
    int jl = tid & 31, chunk = tid >> 5;
    int b = b0 + (blockIdx.x >> 8);
    int tile = blockIdx.x & 255;
    int j = tile * 32 + jl;

    float a0 = g_r[b * TT + tid];
    float a1 = g_r[b * TT + tid + 512];
    float m = fmaxf(a0, a1);
#pragma unroll
    for (int o = 16; o; o >>= 1) m = fmaxf(m, __shfl_xor_sync(~0u, m, o));
    if ((tid & 31) == 0) red[tid >> 5] = m;
    __syncthreads();
    if (tid == 0) {
        float t = red[0];
#pragma unroll
        for (int w = 1; w < 16; w++) t = fmaxf(t, red[w]);
        red[16] = t + GB2;
    }
    __syncthreads();
    float mc = red[16];
    rr[tid] = a0 - mc;
    rr[tid + 512] = a1 - mc;
    __syncthreads();

    const float* gp = g + ((size_t)(b * TT) + (size_t)chunk * 64) * NN + j;
    const float4* rr4 = (const float4*)(rr + chunk * 64);
    float s0 = 0.f, s1 = 0.f, s2 = 0.f, s3 = 0.f;
#pragma unroll 4
    for (int i = 0; i < 16; i++) {
        float4 rv = rr4[i];
        float h0 = gp[(size_t)(4 * i + 0) * NN];
        float h1 = gp[(size_t)(4 * i + 1) * NN];
        float h2 = gp[(size_t)(4 * i + 2) * NN];
        float h3 = gp[(size_t)(4 * i + 3) * NN];
        s0 += ex2(fmaf(h0, C2, rv.x));
        s1 += ex2(fmaf(h1, C2, rv.y));
        s2 += ex2(fmaf(h2, C2, rv.z));
        s3 += ex2(fmaf(h3, C2, rv.w));
    }
    ps[chunk][jl] = (s0 + s1) + (s2 + s3);
    __syncthreads();
    if (chunk == 0) {
        float t = ps[0][jl];
#pragma unroll
        for (int c = 1; c < 16; c++) t += ps[c][jl];
        g_v[b * NN + j] = -(mc + __log2f(t));
    }
}

// ---- row pass, 4 rows/block, v staged in smem ONCE (kills 128MB/launch of
// v re-reads that made R3's k_row 2x the cost of k_col).
// block: 512 thr = 4 rows x 4 quarter-warps. grid: 2 batches * 256 blocks.
__global__ void __launch_bounds__(512) k_row(const float* __restrict__ g, int b0) {
    __shared__ float vs[NN];        // 32KB staged v (shifted by -Mr after max)
    __shared__ float red[17];
    __shared__ float wsum[16];
    int tid = threadIdx.x;
    int b = b0 + (blockIdx.x >> 8);
    int r0 = (blockIdx.x & 255) * 4;

    // stage v + block max
    const float4* vp = (const float4*)(g_v + (size_t)b * NN);
    float m = NEG_BIG;
    float4 hold[4];
#pragma unroll
    for (int k = 0; k < 4; k++) {
        float4 v = vp[tid + 512 * k];
        hold[k] = v;
        m = fmaxf(m, fmaxf(fmaxf(v.x, v.y), fmaxf(v.z, v.w)));
    }
#pragma unroll
    for (int o = 16; o; o >>= 1) m = fmaxf(m, __shfl_xor_sync(~0u, m, o));
    if ((tid & 31) == 0) red[tid >> 5] = m;
    __syncthreads();
    if (tid == 0) {
        float t = red[0];
#pragma unroll
        for (int w = 1; w < 16; w++) t = fmaxf(t, red[w]);
        red[16] = t + GB2;
    }
    __syncthreads();
    float Mr = red[16];
#pragma unroll
    for (int k = 0; k < 4; k++) {
        float4 v = hold[k];
        v.x -= Mr; v.y -= Mr; v.z -= Mr; v.w -= Mr;
        ((float4*)vs)[tid + 512 * k] = v;
    }
    __syncthreads();

    // sum: warp w -> row r0 + (w>>2), quarter (w&3) of 8192 cols
    int w = tid >> 5, l = tid & 31;
    int row = r0 + (w >> 2), q = w & 3;
    const float4* gp = (const float4*)(g + ((size_t)(b * TT + row)) * NN + q * 2048);
    const float4* vq = (const float4*)(vs + q * 2048);
    float s0 = 0.f, s1 = 0.f, s2 = 0.f, s3 = 0.f;
#pragma unroll
    for (int k = 0; k < 16; k++) {
        float4 h = gp[l + 32 * k];
        float4 v = vq[l + 32 * k];
        s0 += ex2(fmaf(h.x, C2, v.x));
        s1 += ex2(fmaf(h.y, C2, v.y));
        s2 += ex2(fmaf(h.z, C2, v.z));
        s3 += ex2(fmaf(h.w, C2, v.w));
    }
    float s = (s0 + s1) + (s2 + s3);
#pragma unroll
    for (int o = 16; o; o >>= 1) s += __shfl_xor_sync(~0u, s, o);
    if (l == 0) wsum[w] = s;
    __syncthreads();
    if (tid < 4) {
        float t = (wsum[4 * tid] + wsum[4 * tid + 1]) +
                  (wsum[4 * tid + 2] + wsum[4 * tid + 3]);
        g_r[b * TT + r0 + tid] = -(Mr + __log2f(t));
    }
}

// ---- final argmax, 4 rows/block, v staged in smem (log domain; no exp needed)
__global__ void __launch_bounds__(512) k_argmax(const float* __restrict__ g,
                                                float* __restrict__ out, int b0) {
    __shared__ float vs[NN];
    __shared__ float wv[16];
    __shared__ int   wi[16];
    int tid = threadIdx.x;
    int b = b0 + (blockIdx.x >> 8);
    int r0 = (blockIdx.x & 255) * 4;

    const float4* vp = (const float4*)(g_v + (size_t)b * NN);
#pragma unroll
    for (int k = 0; k < 4; k++) ((float4*)vs)[tid + 512 * k] = vp[tid + 512 * k];
    __syncthreads();

    int w = tid >> 5, l = tid & 31;
    int row = r0 + (w >> 2), q = w & 3;
    const float4* gp = (const float4*)(g + ((size_t)(b * TT + row)) * NN + q * 2048);
    const float4* vq = (const float4*)(vs + q * 2048);
    float b0v = NEG_BIG, b1v = NEG_BIG, b2v = NEG_BIG, b3v = NEG_BIG;
    int i0 = 0, i1 = 0, i2 = 0, i3 = 0;
#pragma unroll
    for (int k = 0; k < 16; k++) {
        int idx = l + 32 * k;
        float4 h = gp[idx];
        float4 v = vq[idx];
        int j0 = q * 2048 + idx * 4;
        float t0 = fmaf(h.x, C2, v.x), t1 = fmaf(h.y, C2, v.y);
        float t2 = fmaf(h.z, C2, v.z), t3 = fmaf(h.w, C2, v.w);
        if (t0 > b0v) { b0v = t0; i0 = j0; }
        if (t1 > b1v) { b1v = t1; i1 = j0 + 1; }
        if (t2 > b2v) { b2v = t2; i2 = j0 + 2; }
        if (t3 > b3v) { b3v = t3; i3 = j0 + 3; }
    }
    if (b1v > b0v || (b1v == b0v && i1 < i0)) { b0v = b1v; i0 = i1; }
    if (b3v > b2v || (b3v == b2v && i3 < i2)) { b2v = b3v; i2 = i3; }
    if (b2v > b0v || (b2v == b0v && i2 < i0)) { b0v = b2v; i0 = i2; }
#pragma unroll
    for (int o = 16; o; o >>= 1) {
        float bv = __shfl_down_sync(~0u, b0v, o);
        int   iv = __shfl_down_sync(~0u, i0, o);
        if (bv > b0v || (bv == b0v && iv < i0)) { b0v = bv; i0 = iv; }
    }
    if (l == 0) { wv[w] = b0v; wi[w] = i0; }
    __syncthreads();
    if (tid < 4) {
        float bv = wv[4 * tid]; int bi = wi[4 * tid];
#pragma unroll
        for (int c = 1; c < 4; c++) {
            float v = wv[4 * tid + c]; int id = wi[4 * tid + c];
            if (v > bv || (v == bv && id < bi)) { bv = v; bi = id; }
        }
        int o0 = b * TT + r0 + tid;
        out[o0] = 1.0f;                 // s + stopgrad(1-s) == 1.0 exactly; mask all-true
        out[BB * TT + o0] = (float)bi;  // selected index
    }
}

extern "C" void kernel_launch(void* const* d_in, const int* in_sizes, int n_in,
                              void* d_out, int out_size) {
    // x and routing_token are mathematically dead: scores cancel in the first
    // axis=-2 normalization. Only gumbel matters.
    const float* g = (const float*)d_in[2];
    float* out = (float*)d_out;

    k_init<<<8, 512>>>();
    // batch-pair sets: keep 64MB gumbel slice L2-resident across all 16 sweeps
    for (int b0 = 0; b0 < BB; b0 += 2) {
        for (int it = 0; it < 8; it++) {
            k_col<<<512, 512>>>(g, b0);
            if (it < 7) k_row<<<512, 512>>>(g, b0);
        }
        k_argmax<<<512, 512>>>(g, out, b0);
    }
}

// round 13
// speedup vs baseline: 2.8814x; 1.1516x over previous
#include <cuda_runtime.h>
#include <cstdint>

// Shapes fixed by setup_inputs: gumbel (4, 1024, 8192)
#define BB 4
#define NN 8192
#define TT 1024
#define C2 1.4426950408889634f     // log2(e): all work in base-2 log domain
#define GB2 66.6f                  // safe offset bits (gumbel <= 46.05 nats = 66.44 bits)
#define NEG_BIG (-3.402823466e38f)

// Scratch (device globals; no allocation allowed)
__device__ float g_r[BB * TT];     // row offsets r_i (log2 domain)
__device__ float g_v[BB * NN];     // col offsets c_j (log2 domain)

__device__ __forceinline__ float ex2(float x) {
    float r; asm("ex2.approx.ftz.f32 %0, %1;" : "=f"(r) : "f"(x)); return r;
}

// ---- col pass: c_j = -(Mc + log2 sum_i 2^(g*C2 + r_i - Mc)), Mc = max r + GB2
// 64-col tiles, float2 lanes (128B x 2 rows per warp step).
// block: 1024 thr = 32 chunks x 32 rows. grid: 2 batches * 128 tiles.
__global__ void __launch_bounds__(1024) k_col(const float* __restrict__ g, int b0, int first) {
    __shared__ float rr[TT];        // r - Mc
    __shared__ float red[33];
    __shared__ float2 ps[32][32];
    __shared__ float2 ps2[8][32];   // stage-1 partials (separate buffer: no race)
    int tid = threadIdx.x;
    int jl = tid & 31, chunk = tid >> 5;
    int b = b0 + (blockIdx.x >> 7);
    int tile = blockIdx.x & 127;
    int j = tile * 64 + 2 * jl;

    float mc;
    if (first) {
        mc = GB2;                            // r == 0 on iteration 0
        rr[tid] = -GB2;
    } else {
        float a0 = g_r[b * TT + tid];
        float m = a0;
#pragma unroll
        for (int o = 16; o; o >>= 1) m = fmaxf(m, __shfl_xor_sync(~0u, m, o));
        if ((tid & 31) == 0) red[tid >> 5] = m;
        __syncthreads();
        if (tid == 0) {
            float t = red[0];
#pragma unroll
            for (int w = 1; w < 32; w++) t = fmaxf(t, red[w]);
            red[32] = t + GB2;
        }
        __syncthreads();
        mc = red[32];
        rr[tid] = a0 - mc;
    }
    __syncthreads();

    const float* gp = g + ((size_t)(b * TT) + (size_t)chunk * 32) * NN + j;
    const float* rp = rr + chunk * 32;
    float sx0 = 0.f, sy0 = 0.f, sx1 = 0.f, sy1 = 0.f;
#pragma unroll 4
    for (int i = 0; i < 32; i += 2) {
        float2 h0 = *(const float2*)(gp + (size_t)i * NN);
        float2 h1 = *(const float2*)(gp + (size_t)(i + 1) * NN);
        float r0 = rp[i], r1 = rp[i + 1];
        sx0 += ex2(fmaf(h0.x, C2, r0));
        sy0 += ex2(fmaf(h0.y, C2, r0));
        sx1 += ex2(fmaf(h1.x, C2, r1));
        sy1 += ex2(fmaf(h1.y, C2, r1));
    }
    ps[chunk][jl] = make_float2(sx0 + sx1, sy0 + sy1);
    __syncthreads();
    // two-stage reduce into a DISJOINT buffer (R11 failed on ps->ps aliasing)
    if (chunk < 8) {
        float tx = ps[4 * chunk][jl].x, ty = ps[4 * chunk][jl].y;
#pragma unroll
        for (int c = 1; c < 4; c++) {
            tx += ps[4 * chunk + c][jl].x;
            ty += ps[4 * chunk + c][jl].y;
        }
        ps2[chunk][jl] = make_float2(tx, ty);
    }
    __syncthreads();
    if (chunk == 0) {
        float tx = ps2[0][jl].x, ty = ps2[0][jl].y;
#pragma unroll
        for (int c = 1; c < 8; c++) { tx += ps2[c][jl].x; ty += ps2[c][jl].y; }
        g_v[b * NN + j]     = -(mc + __log2f(tx));
        g_v[b * NN + j + 1] = -(mc + __log2f(ty));
    }
}

// ---- row pass, 4 rows/block, v staged in smem once. grid: 2 batches * 256.
__global__ void __launch_bounds__(512) k_row(const float* __restrict__ g, int b0) {
    __shared__ float vs[NN];        // 32KB staged v (shifted by -Mr)
    __shared__ float red[17];
    __shared__ float wsum[16];
    int tid = threadIdx.x;
    int b = b0 + (blockIdx.x >> 8);
    int r0 = (blockIdx.x & 255) * 4;

    const float4* vp = (const float4*)(g_v + (size_t)b * NN);
    float m = NEG_BIG;
    float4 hold[4];
#pragma unroll
    for (int k = 0; k < 4; k++) {
        float4 v = vp[tid + 512 * k];
        hold[k] = v;
        m = fmaxf(m, fmaxf(fmaxf(v.x, v.y), fmaxf(v.z, v.w)));
    }
#pragma unroll
    for (int o = 16; o; o >>= 1) m = fmaxf(m, __shfl_xor_sync(~0u, m, o));
    if ((tid & 31) == 0) red[tid >> 5] = m;
    __syncthreads();
    if (tid == 0) {
        float t = red[0];
#pragma unroll
        for (int w = 1; w < 16; w++) t = fmaxf(t, red[w]);
        red[16] = t + GB2;
    }
    __syncthreads();
    float Mr = red[16];
#pragma unroll
    for (int k = 0; k < 4; k++) {
        float4 v = hold[k];
        v.x -= Mr; v.y -= Mr; v.z -= Mr; v.w -= Mr;
        ((float4*)vs)[tid + 512 * k] = v;
    }
    __syncthreads();

    int w = tid >> 5, l = tid & 31;
    int row = r0 + (w >> 2), q = w & 3;
    const float4* gp = (const float4*)(g + ((size_t)(b * TT + row)) * NN + q * 2048);
    const float4* vq = (const float4*)(vs + q * 2048);
    float s0 = 0.f, s1 = 0.f, s2 = 0.f, s3 = 0.f;
#pragma unroll
    for (int k = 0; k < 16; k++) {
        float4 h = gp[l + 32 * k];
        float4 v = vq[l + 32 * k];
        s0 += ex2(fmaf(h.x, C2, v.x));
        s1 += ex2(fmaf(h.y, C2, v.y));
        s2 += ex2(fmaf(h.z, C2, v.z));
        s3 += ex2(fmaf(h.w, C2, v.w));
    }
    float s = (s0 + s1) + (s2 + s3);
#pragma unroll
    for (int o = 16; o; o >>= 1) s += __shfl_xor_sync(~0u, s, o);
    if (l == 0) wsum[w] = s;
    __syncthreads();
    if (tid < 4) {
        float t = (wsum[4 * tid] + wsum[4 * tid + 1]) +
                  (wsum[4 * tid + 2] + wsum[4 * tid + 3]);
        g_r[b * TT + r0 + tid] = -(Mr + __log2f(t));
    }
}

// ---- final argmax, 4 rows/block, v staged in smem (log domain)
__global__ void __launch_bounds__(512) k_argmax(const float* __restrict__ g,
                                                float* __restrict__ out, int b0) {
    __shared__ float vs[NN];
    __shared__ float wv[16];
    __shared__ int   wi[16];
    int tid = threadIdx.x;
    int b = b0 + (blockIdx.x >> 8);
    int r0 = (blockIdx.x & 255) * 4;

    const float4* vp = (const float4*)(g_v + (size_t)b * NN);
#pragma unroll
    for (int k = 0; k < 4; k++) ((float4*)vs)[tid + 512 * k] = vp[tid + 512 * k];
    __syncthreads();

    int w = tid >> 5, l = tid & 31;
    int row = r0 + (w >> 2), q = w & 3;
    const float4* gp = (const float4*)(g + ((size_t)(b * TT + row)) * NN + q * 2048);
    const float4* vq = (const float4*)(vs + q * 2048);
    float b0v = NEG_BIG, b1v = NEG_BIG, b2v = NEG_BIG, b3v = NEG_BIG;
    int i0 = 0, i1 = 0, i2 = 0, i3 = 0;
#pragma unroll
    for (int k = 0; k < 16; k++) {
        int idx = l + 32 * k;
        float4 h = gp[idx];
        float4 v = vq[idx];
        int j0 = q * 2048 + idx * 4;
        float t0 = fmaf(h.x, C2, v.x), t1 = fmaf(h.y, C2, v.y);
        float t2 = fmaf(h.z, C2, v.z), t3 = fmaf(h.w, C2, v.w);
        if (t0 > b0v) { b0v = t0; i0 = j0; }
        if (t1 > b1v) { b1v = t1; i1 = j0 + 1; }
        if (t2 > b2v) { b2v = t2; i2 = j0 + 2; }
        if (t3 > b3v) { b3v = t3; i3 = j0 + 3; }
    }
    if (b1v > b0v || (b1v == b0v && i1 < i0)) { b0v = b1v; i0 = i1; }
    if (b3v > b2v || (b3v == b2v && i3 < i2)) { b2v = b3v; i2 = i3; }
    if (b2v > b0v || (b2v == b0v && i2 < i0)) { b0v = b2v; i0 = i2; }
#pragma unroll
    for (int o = 16; o; o >>= 1) {
        float bv = __shfl_down_sync(~0u, b0v, o);
        int   iv = __shfl_down_sync(~0u, i0, o);
        if (bv > b0v || (bv == b0v && iv < i0)) { b0v = bv; i0 = iv; }
    }
    if (l == 0) { wv[w] = b0v; wi[w] = i0; }
    __syncthreads();
    if (tid < 4) {
        float bv = wv[4 * tid]; int bi = wi[4 * tid];
#pragma unroll
        for (int c = 1; c < 4; c++) {
            float v = wv[4 * tid + c]; int id = wi[4 * tid + c];
            if (v > bv || (v == bv && id < bi)) { bv = v; bi = id; }
        }
        int o0 = b * TT + r0 + tid;
        out[o0] = 1.0f;                 // s + stopgrad(1-s) == 1.0 exactly; mask all-true
        out[BB * TT + o0] = (float)bi;  // selected index
    }
}

extern "C" void kernel_launch(void* const* d_in, const int* in_sizes, int n_in,
                              void* d_out, int out_size) {
    // x and routing_token are mathematically dead: scores cancel in the first
    // axis=-2 normalization. Only gumbel matters.
    const float* g = (const float*)d_in[2];
    float* out = (float*)d_out;

    // batch-pair sets: keep 64MB gumbel slice L2-resident across all 16 sweeps
    for (int b0 = 0; b0 < BB; b0 += 2) {
        for (int it = 0; it < 8; it++) {
            k_col<<<256, 1024>>>(g, b0, it == 0 ? 1 : 0);
            if (it < 7) k_row<<<512, 512>>>(g, b0);
        }
        k_argmax<<<512, 512>>>(g, out, b0);
    }
}

// round 14
// speedup vs baseline: 2.9521x; 1.0245x over previous
#include <cuda_runtime.h>
#include <cstdint>

// Shapes fixed by setup_inputs: gumbel (4, 1024, 8192)
#define BB 4
#define NN 8192
#define TT 1024
#define C2 1.4426950408889634f     // log2(e): all work in base-2 log domain
#define GB2 66.6f                  // safe offset bits (gumbel <= 46.05 nats = 66.44 bits)
#define NEG_BIG (-3.402823466e38f)

// Scratch (device globals; no allocation allowed)
__device__ float g_r[BB * TT];        // row offsets r_i (log2 domain)
__device__ float g_v[BB * NN];        // col offsets c_j (log2 domain)
__device__ float g_cmaxb[BB * 128];   // per-tile max of c (written by k_col)
__device__ float g_rmaxb[BB * 256];   // per-block max of r (written by k_row)

__device__ __forceinline__ float ex2(float x) {
    float r; asm("ex2.approx.ftz.f32 %0, %1;" : "=f"(r) : "f"(x)); return r;
}

// ---- col pass: c_j = -(Mc + log2 sum_i 2^(g*C2 + r_i - Mc)), Mc = max r + GB2
// 64-col tiles, float2 lanes. block: 1024 thr = 32 chunks x 32 rows.
// grid: 2 batches * 128 tiles. Mc comes from k_row's per-block rmax table.
__global__ void __launch_bounds__(1024) k_col(const float* __restrict__ g, int b0, int first) {
    __shared__ float rr[TT];        // r - Mc
    __shared__ float mcs;
    __shared__ float2 ps[32][32];
    __shared__ float2 ps2[8][32];   // stage-1 partials (disjoint buffer — R11 lesson)
    int tid = threadIdx.x;
    int jl = tid & 31, chunk = tid >> 5;
    int b = b0 + (blockIdx.x >> 7);
    int tile = blockIdx.x & 127;
    int j = tile * 64 + 2 * jl;

    float mc;
    if (first) {
        mc = GB2;                            // r == 0 on iteration 0
        rr[tid] = -GB2;
        __syncthreads();
    } else {
        float a0 = g_r[b * TT + tid];        // issue early; overlaps warp-0 fold
        if (tid < 32) {
            float m = NEG_BIG;
#pragma unroll
            for (int q = 0; q < 8; q++) m = fmaxf(m, g_rmaxb[b * 256 + tid * 8 + q]);
#pragma unroll
            for (int o = 16; o; o >>= 1) m = fmaxf(m, __shfl_xor_sync(~0u, m, o));
            if (tid == 0) mcs = m + GB2;
        }
        __syncthreads();
        mc = mcs;
        rr[tid] = a0 - mc;
        __syncthreads();
    }

    const float* gp = g + ((size_t)(b * TT) + (size_t)chunk * 32) * NN + j;
    const float* rp = rr + chunk * 32;
    float sx0 = 0.f, sy0 = 0.f, sx1 = 0.f, sy1 = 0.f;
#pragma unroll 4
    for (int i = 0; i < 32; i += 2) {
        float2 h0 = *(const float2*)(gp + (size_t)i * NN);
        float2 h1 = *(const float2*)(gp + (size_t)(i + 1) * NN);
        float r0 = rp[i], r1 = rp[i + 1];
        sx0 += ex2(fmaf(h0.x, C2, r0));
        sy0 += ex2(fmaf(h0.y, C2, r0));
        sx1 += ex2(fmaf(h1.x, C2, r1));
        sy1 += ex2(fmaf(h1.y, C2, r1));
    }
    ps[chunk][jl] = make_float2(sx0 + sx1, sy0 + sy1);
    __syncthreads();
    if (chunk < 8) {
        float tx = ps[4 * chunk][jl].x, ty = ps[4 * chunk][jl].y;
#pragma unroll
        for (int c = 1; c < 4; c++) {
            tx += ps[4 * chunk + c][jl].x;
            ty += ps[4 * chunk + c][jl].y;
        }
        ps2[chunk][jl] = make_float2(tx, ty);
    }
    __syncthreads();
    if (chunk == 0) {
        float tx = ps2[0][jl].x, ty = ps2[0][jl].y;
#pragma unroll
        for (int c = 1; c < 8; c++) { tx += ps2[c][jl].x; ty += ps2[c][jl].y; }
        float cx = -(mc + __log2f(tx));
        float cy = -(mc + __log2f(ty));
        g_v[b * NN + j]     = cx;
        g_v[b * NN + j + 1] = cy;
        // per-tile cmax handoff for k_row's Mr (removes its block reduce)
        float m = fmaxf(cx, cy);
#pragma unroll
        for (int o = 16; o; o >>= 1) m = fmaxf(m, __shfl_xor_sync(~0u, m, o));
        if (jl == 0) g_cmaxb[b * 128 + tile] = m;
    }
}

// ---- row pass, 4 rows/block, v staged in smem once. grid: 2 batches * 256.
// Mr comes from k_col's per-tile cmax table (warp-0 fold, overlapped with v loads).
__global__ void __launch_bounds__(512) k_row(const float* __restrict__ g, int b0) {
    __shared__ float vs[NN];        // 32KB staged v (shifted by -Mr)
    __shared__ float Mrs;
    __shared__ float wsum[16];
    int tid = threadIdx.x;
    int b = b0 + (blockIdx.x >> 8);
    int r0 = (blockIdx.x & 255) * 4;

    const float4* vp = (const float4*)(g_v + (size_t)b * NN);
    float4 hold[4];
#pragma unroll
    for (int k = 0; k < 4; k++) hold[k] = vp[tid + 512 * k];   // in flight early
    if (tid < 32) {
        float m = NEG_BIG;
#pragma unroll
        for (int q = 0; q < 4; q++) m = fmaxf(m, g_cmaxb[b * 128 + tid * 4 + q]);
#pragma unroll
        for (int o = 16; o; o >>= 1) m = fmaxf(m, __shfl_xor_sync(~0u, m, o));
        if (tid == 0) Mrs = m + GB2;
    }
    __syncthreads();
    float Mr = Mrs;
#pragma unroll
    for (int k = 0; k < 4; k++) {
        float4 v = hold[k];
        v.x -= Mr; v.y -= Mr; v.z -= Mr; v.w -= Mr;
        ((float4*)vs)[tid + 512 * k] = v;
    }
    __syncthreads();

    int w = tid >> 5, l = tid & 31;
    int row = r0 + (w >> 2), q = w & 3;
    const float4* gp = (const float4*)(g + ((size_t)(b * TT + row)) * NN + q * 2048);
    const float4* vq = (const float4*)(vs + q * 2048);
    float s0 = 0.f, s1 = 0.f, s2 = 0.f, s3 = 0.f;
#pragma unroll
    for (int k = 0; k < 16; k++) {
        float4 h = gp[l + 32 * k];
        float4 v = vq[l + 32 * k];
        s0 += ex2(fmaf(h.x, C2, v.x));
        s1 += ex2(fmaf(h.y, C2, v.y));
        s2 += ex2(fmaf(h.z, C2, v.z));
        s3 += ex2(fmaf(h.w, C2, v.w));
    }
    float s = (s0 + s1) + (s2 + s3);
#pragma unroll
    for (int o = 16; o; o >>= 1) s += __shfl_xor_sync(~0u, s, o);
    if (l == 0) wsum[w] = s;
    __syncthreads();
    float rloc = NEG_BIG;
    if (tid < 4) {
        float t = (wsum[4 * tid] + wsum[4 * tid + 1]) +
                  (wsum[4 * tid + 2] + wsum[4 * tid + 3]);
        rloc = -(Mr + __log2f(t));
        g_r[b * TT + r0 + tid] = rloc;
    }
    if (tid < 32) {
        // fold lanes 0..3 into lane 0 (others hold NEG_BIG)
        float m = rloc;
        m = fmaxf(m, __shfl_xor_sync(~0u, m, 1));
        m = fmaxf(m, __shfl_xor_sync(~0u, m, 2));
        if (tid == 0) g_rmaxb[b * 256 + (blockIdx.x & 255)] = m;
    }
}

// ---- final argmax, 4 rows/block, v staged in smem (log domain)
__global__ void __launch_bounds__(512) k_argmax(const float* __restrict__ g,
                                                float* __restrict__ out, int b0) {
    __shared__ float vs[NN];
    __shared__ float wv[16];
    __shared__ int   wi[16];
    int tid = threadIdx.x;
    int b = b0 + (blockIdx.x >> 8);
    int r0 = (blockIdx.x & 255) * 4;

    const float4* vp = (const float4*)(g_v + (size_t)b * NN);
#pragma unroll
    for (int k = 0; k < 4; k++) ((float4*)vs)[tid + 512 * k] = vp[tid + 512 * k];
    __syncthreads();

    int w = tid >> 5, l = tid & 31;
    int row = r0 + (w >> 2), q = w & 3;
    const float4* gp = (const float4*)(g + ((size_t)(b * TT + row)) * NN + q * 2048);
    const float4* vq = (const float4*)(vs + q * 2048);
    float b0v = NEG_BIG, b1v = NEG_BIG, b2v = NEG_BIG, b3v = NEG_BIG;
    int i0 = 0, i1 = 0, i2 = 0, i3 = 0;
#pragma unroll
    for (int k = 0; k < 16; k++) {
        int idx = l + 32 * k;
        float4 h = gp[idx];
        float4 v = vq[idx];
        int j0 = q * 2048 + idx * 4;
        float t0 = fmaf(h.x, C2, v.x), t1 = fmaf(h.y, C2, v.y);
        float t2 = fmaf(h.z, C2, v.z), t3 = fmaf(h.w, C2, v.w);
        if (t0 > b0v) { b0v = t0; i0 = j0; }
        if (t1 > b1v) { b1v = t1; i1 = j0 + 1; }
        if (t2 > b2v) { b2v = t2; i2 = j0 + 2; }
        if (t3 > b3v) { b3v = t3; i3 = j0 + 3; }
    }
    if (b1v > b0v || (b1v == b0v && i1 < i0)) { b0v = b1v; i0 = i1; }
    if (b3v > b2v || (b3v == b2v && i3 < i2)) { b2v = b3v; i2 = i3; }
    if (b2v > b0v || (b2v == b0v && i2 < i0)) { b0v = b2v; i0 = i2; }
#pragma unroll
    for (int o = 16; o; o >>= 1) {
        float bv = __shfl_down_sync(~0u, b0v, o);
        int   iv = __shfl_down_sync(~0u, i0, o);
        if (bv > b0v || (bv == b0v && iv < i0)) { b0v = bv; i0 = iv; }
    }
    if (l == 0) { wv[w] = b0v; wi[w] = i0; }
    __syncthreads();
    if (tid < 4) {
        float bv = wv[4 * tid]; int bi = wi[4 * tid];
#pragma unroll
        for (int c = 1; c < 4; c++) {
            float v = wv[4 * tid + c]; int id = wi[4 * tid + c];
            if (v > bv || (v == bv && id < bi)) { bv = v; bi = id; }
        }
        int o0 = b * TT + r0 + tid;
        out[o0] = 1.0f;                 // s + stopgrad(1-s) == 1.0 exactly; mask all-true
        out[BB * TT + o0] = (float)bi;  // selected index
    }
}

extern "C" void kernel_launch(void* const* d_in, const int* in_sizes, int n_in,
                              void* d_out, int out_size) {
    // x and routing_token are mathematically dead: scores cancel in the first
    // axis=-2 normalization. Only gumbel matters.
    const float* g = (const float*)d_in[2];
    float* out = (float*)d_out;

    // batch-pair sets: keep 64MB gumbel slice L2-resident across all 16 sweeps
    for (int b0 = 0; b0 < BB; b0 += 2) {
        for (int it = 0; it < 8; it++) {
            k_col<<<256, 1024>>>(g, b0, it == 0 ? 1 : 0);
            if (it < 7) k_row<<<512, 512>>>(g, b0);
        }
        k_argmax<<<512, 512>>>(g, out, b0);
    }
}

// round 15
// speedup vs baseline: 3.1805x; 1.0774x over previous
#include <cuda_runtime.h>
#include <cstdint>

// Shapes fixed by setup_inputs: gumbel (4, 1024, 8192)
#define BB 4
#define NN 8192
#define TT 1024
#define C2 1.4426950408889634f     // log2(e): all work in base-2 log domain
#define GB2 66.6f                  // safe offset bits (gumbel <= 46.05 nats = 66.44 bits)
#define NEG_BIG (-3.402823466e38f)

// Scratch (device globals; no allocation allowed)
__device__ float g_r[BB * TT];        // row offsets r_i (log2 domain)
__device__ float g_v[BB * NN];        // col offsets c_j (log2 domain)
__device__ float g_cmaxb[BB * 128];   // per-tile max of c (written by k_col)
__device__ float g_rmaxb[BB * 256];   // per-block max of r (written by k_row)

__device__ __forceinline__ float ex2(float x) {
    float r; asm("ex2.approx.ftz.f32 %0, %1;" : "=f"(r) : "f"(x)); return r;
}

// ---- col pass: c_j = -(Mc + log2 sum_i 2^(g*C2 + r_i - Mc)), Mc = max r + GB2
// 64-col tiles, float2 lanes. block: 1024 thr = 32 chunks x 32 rows.
// grid: 2 batches * 128 tiles. Mc from k_row's per-block rmax table.
__global__ void __launch_bounds__(1024) k_col(const float* __restrict__ g, int b0, int first) {
    cudaGridDependencySynchronize();    // PDL: MUST precede any global read (R9 lesson)
    __shared__ float rr[TT];            // r - Mc
    __shared__ float mcs;
    __shared__ float2 ps[32][32];
    __shared__ float2 ps2[8][32];       // stage-1 partials (disjoint buffer — R11 lesson)
    int tid = threadIdx.x;
    int jl = tid & 31, chunk = tid >> 5;
    int b = b0 + (blockIdx.x >> 7);
    int tile = blockIdx.x & 127;
    int j = tile * 64 + 2 * jl;

    float mc;
    if (first) {
        mc = GB2;                            // r == 0 on iteration 0
        rr[tid] = -GB2;
        __syncthreads();
    } else {
        float a0 = g_r[b * TT + tid];        // issue early; overlaps warp-0 fold
        if (tid < 32) {
            float m = NEG_BIG;
#pragma unroll
            for (int q = 0; q < 8; q++) m = fmaxf(m, g_rmaxb[b * 256 + tid * 8 + q]);
#pragma unroll
            for (int o = 16; o; o >>= 1) m = fmaxf(m, __shfl_xor_sync(~0u, m, o));
            if (tid == 0) mcs = m + GB2;
        }
        __syncthreads();
        mc = mcs;
        rr[tid] = a0 - mc;
        __syncthreads();
    }

    const float* gp = g + ((size_t)(b * TT) + (size_t)chunk * 32) * NN + j;
    const float* rp = rr + chunk * 32;
    float sx0 = 0.f, sy0 = 0.f, sx1 = 0.f, sy1 = 0.f;
#pragma unroll 4
    for (int i = 0; i < 32; i += 2) {
        float2 h0 = *(const float2*)(gp + (size_t)i * NN);
        float2 h1 = *(const float2*)(gp + (size_t)(i + 1) * NN);
        float r0 = rp[i], r1 = rp[i + 1];
        sx0 += ex2(fmaf(h0.x, C2, r0));
        sy0 += ex2(fmaf(h0.y, C2, r0));
        sx1 += ex2(fmaf(h1.x, C2, r1));
        sy1 += ex2(fmaf(h1.y, C2, r1));
    }
    ps[chunk][jl] = make_float2(sx0 + sx1, sy0 + sy1);
    __syncthreads();
    if (chunk < 8) {
        float tx = ps[4 * chunk][jl].x, ty = ps[4 * chunk][jl].y;
#pragma unroll
        for (int c = 1; c < 4; c++) {
            tx += ps[4 * chunk + c][jl].x;
            ty += ps[4 * chunk + c][jl].y;
        }
        ps2[chunk][jl] = make_float2(tx, ty);
    }
    __syncthreads();
    if (chunk == 0) {
        float tx = ps2[0][jl].x, ty = ps2[0][jl].y;
#pragma unroll
        for (int c = 1; c < 8; c++) { tx += ps2[c][jl].x; ty += ps2[c][jl].y; }
        float cx = -(mc + __log2f(tx));
        float cy = -(mc + __log2f(ty));
        g_v[b * NN + j]     = cx;
        g_v[b * NN + j + 1] = cy;
        // per-tile cmax handoff for k_row's Mr (removes its block reduce)
        float m = fmaxf(cx, cy);
#pragma unroll
        for (int o = 16; o; o >>= 1) m = fmaxf(m, __shfl_xor_sync(~0u, m, o));
        if (jl == 0) g_cmaxb[b * 128 + tile] = m;
    }
}

// ---- row pass, 4 rows/block, v staged in smem once. grid: 2 batches * 256.
// Mr from k_col's per-tile cmax table (warp-0 fold, overlapped with v loads).
__global__ void __launch_bounds__(512) k_row(const float* __restrict__ g, int b0) {
    cudaGridDependencySynchronize();    // PDL: MUST precede any global read
    __shared__ float vs[NN];            // 32KB staged v (shifted by -Mr)
    __shared__ float Mrs;
    __shared__ float wsum[16];
    int tid = threadIdx.x;
    int b = b0 + (blockIdx.x >> 8);
    int r0 = (blockIdx.x & 255) * 4;

    const float4* vp = (const float4*)(g_v + (size_t)b * NN);
    float4 hold[4];
#pragma unroll
    for (int k = 0; k < 4; k++) hold[k] = vp[tid + 512 * k];   // in flight early
    if (tid < 32) {
        float m = NEG_BIG;
#pragma unroll
        for (int q = 0; q < 4; q++) m = fmaxf(m, g_cmaxb[b * 128 + tid * 4 + q]);
#pragma unroll
        for (int o = 16; o; o >>= 1) m = fmaxf(m, __shfl_xor_sync(~0u, m, o));
        if (tid == 0) Mrs = m + GB2;
    }
    __syncthreads();
    float Mr = Mrs;
#pragma unroll
    for (int k = 0; k < 4; k++) {
        float4 v = hold[k];
        v.x -= Mr; v.y -= Mr; v.z -= Mr; v.w -= Mr;
        ((float4*)vs)[tid + 512 * k] = v;
    }
    __syncthreads();

    int w = tid >> 5, l = tid & 31;
    int row = r0 + (w >> 2), q = w & 3;
    const float4* gp = (const float4*)(g + ((size_t)(b * TT + row)) * NN + q * 2048);
    const float4* vq = (const float4*)(vs + q * 2048);
    float s0 = 0.f, s1 = 0.f, s2 = 0.f, s3 = 0.f;
#pragma unroll
    for (int k = 0; k < 16; k++) {
        float4 h = gp[l + 32 * k];
        float4 v = vq[l + 32 * k];
        s0 += ex2(fmaf(h.x, C2, v.x));
        s1 += ex2(fmaf(h.y, C2, v.y));
        s2 += ex2(fmaf(h.z, C2, v.z));
        s3 += ex2(fmaf(h.w, C2, v.w));
    }
    float s = (s0 + s1) + (s2 + s3);
#pragma unroll
    for (int o = 16; o; o >>= 1) s += __shfl_xor_sync(~0u, s, o);
    if (l == 0) wsum[w] = s;
    __syncthreads();
    float rloc = NEG_BIG;
    if (tid < 4) {
        float t = (wsum[4 * tid] + wsum[4 * tid + 1]) +
                  (wsum[4 * tid + 2] + wsum[4 * tid + 3]);
        rloc = -(Mr + __log2f(t));
        g_r[b * TT + r0 + tid] = rloc;
    }
    if (tid < 32) {
        float m = rloc;
        m = fmaxf(m, __shfl_xor_sync(~0u, m, 1));
        m = fmaxf(m, __shfl_xor_sync(~0u, m, 2));
        if (tid == 0) g_rmaxb[b * 256 + (blockIdx.x & 255)] = m;
    }
}

// ---- final argmax, 4 rows/block, v staged in smem (log domain)
__global__ void __launch_bounds__(512) k_argmax(const float* __restrict__ g,
                                                float* __restrict__ out, int b0) {
    cudaGridDependencySynchronize();    // PDL: MUST precede any global read
    __shared__ float vs[NN];
    __shared__ float wv[16];
    __shared__ int   wi[16];
    int tid = threadIdx.x;
    int b = b0 + (blockIdx.x >> 8);
    int r0 = (blockIdx.x & 255) * 4;

    const float4* vp = (const float4*)(g_v + (size_t)b * NN);
#pragma unroll
    for (int k = 0; k < 4; k++) ((float4*)vs)[tid + 512 * k] = vp[tid + 512 * k];
    __syncthreads();

    int w = tid >> 5, l = tid & 31;
    int row = r0 + (w >> 2), q = w & 3;
    const float4* gp = (const float4*)(g + ((size_t)(b * TT + row)) * NN + q * 2048);
    const float4* vq = (const float4*)(vs + q * 2048);
    float b0v = NEG_BIG, b1v = NEG_BIG, b2v = NEG_BIG, b3v = NEG_BIG;
    int i0 = 0, i1 = 0, i2 = 0, i3 = 0;
#pragma unroll
    for (int k = 0; k < 16; k++) {
        int idx = l + 32 * k;
        float4 h = gp[idx];
        float4 v = vq[idx];
        int j0 = q * 2048 + idx * 4;
        float t0 = fmaf(h.x, C2, v.x), t1 = fmaf(h.y, C2, v.y);
        float t2 = fmaf(h.z, C2, v.z), t3 = fmaf(h.w, C2, v.w);
        if (t0 > b0v) { b0v = t0; i0 = j0; }
        if (t1 > b1v) { b1v = t1; i1 = j0 + 1; }
        if (t2 > b2v) { b2v = t2; i2 = j0 + 2; }
        if (t3 > b3v) { b3v = t3; i3 = j0 + 3; }
    }
    if (b1v > b0v || (b1v == b0v && i1 < i0)) { b0v = b1v; i0 = i1; }
    if (b3v > b2v || (b3v == b2v && i3 < i2)) { b2v = b3v; i2 = i3; }
    if (b2v > b0v || (b2v == b0v && i2 < i0)) { b0v = b2v; i0 = i2; }
#pragma unroll
    for (int o = 16; o; o >>= 1) {
        float bv = __shfl_down_sync(~0u, b0v, o);
        int   iv = __shfl_down_sync(~0u, i0, o);
        if (bv > b0v || (bv == b0v && iv < i0)) { b0v = bv; i0 = iv; }
    }
    if (l == 0) { wv[w] = b0v; wi[w] = i0; }
    __syncthreads();
    if (tid < 4) {
        float bv = wv[4 * tid]; int bi = wi[4 * tid];
#pragma unroll
        for (int c = 1; c < 4; c++) {
            float v = wv[4 * tid + c]; int id = wi[4 * tid + c];
            if (v > bv || (v == bv && id < bi)) { bv = v; bi = id; }
        }
        int o0 = b * TT + r0 + tid;
        out[o0] = 1.0f;                 // s + stopgrad(1-s) == 1.0 exactly; mask all-true
        out[BB * TT + o0] = (float)bi;  // selected index
    }
}

// Launch with programmatic stream serialization so each kernel's launch
// setup overlaps its predecessor's tail.
template <typename... Args>
static void launch_pdl(void (*fn)(Args...), dim3 grid, dim3 block, Args... args) {
    cudaLaunchConfig_t cfg = {};
    cfg.gridDim = grid;
    cfg.blockDim = block;
    cfg.stream = 0;
    cudaLaunchAttribute attr[1];
    attr[0].id = cudaLaunchAttributeProgrammaticStreamSerialization;
    attr[0].val.programmaticStreamSerializationAllowed = 1;
    cfg.attrs = attr;
    cfg.numAttrs = 1;
    cudaLaunchKernelEx(&cfg, fn, args...);
}

extern "C" void kernel_launch(void* const* d_in, const int* in_sizes, int n_in,
                              void* d_out, int out_size) {
    // x and routing_token are mathematically dead: scores cancel in the first
    // axis=-2 normalization. Only gumbel matters.
    const float* g = (const float*)d_in[2];
    float* out = (float*)d_out;

    // batch-pair sets: keep 64MB gumbel slice L2-resident across all 16 sweeps
    for (int b0 = 0; b0 < BB; b0 += 2) {
        for (int it = 0; it < 8; it++) {
            launch_pdl(k_col, dim3(256), dim3(1024), g, b0, it == 0 ? 1 : 0);
            if (it < 7) launch_pdl(k_row, dim3(512), dim3(512), g, b0);
        }
        launch_pdl(k_argmax, dim3(512), dim3(512), g, out, b0);
    }
}

// round 16
// speedup vs baseline: 3.5726x; 1.1233x over previous
#include <cuda_runtime.h>
#include <cstdint>

// Shapes fixed by setup_inputs: gumbel (4, 1024, 8192)
#define BB 4
#define NN 8192
#define TT 1024
#define C2 1.4426950408889634f     // log2(e): all work in base-2 log domain
#define GB2 66.6f                  // safe offset bits (gumbel <= 46.05 nats = 66.44 bits)
#define NEG_BIG (-3.402823466e38f)

// Scratch (device globals; no allocation allowed)
__device__ float g_r[BB * TT];        // row offsets r_i (log2 domain)
__device__ float g_v[BB * NN];        // col offsets c_j (log2 domain)
__device__ float g_cmaxb[BB * 128];   // per-tile max of c (written by k_col)
__device__ float g_rmaxb[BB * 128];   // per-block max of r (written by k_row)

__device__ __forceinline__ float ex2(float x) {
    float r; asm("ex2.approx.ftz.f32 %0, %1;" : "=f"(r) : "f"(x)); return r;
}

// ---- col pass: c_j = -(Mc + log2 sum_i 2^(g*C2 + r_i - Mc)), Mc = max r + GB2
// 64-col tiles, float2 lanes. block: 1024 thr = 32 chunks x 32 rows.
// grid: 2 batches * 128 tiles. Mc from k_row's per-block rmax table.
__global__ void __launch_bounds__(1024) k_col(const float* __restrict__ g, int b0, int first) {
    cudaGridDependencySynchronize();    // PDL: MUST precede any global read (R9 lesson)
    __shared__ float rr[TT];            // r - Mc
    __shared__ float mcs;
    __shared__ float2 ps[32][32];
    __shared__ float2 ps2[8][32];       // stage-1 partials (disjoint buffer — R11 lesson)
    int tid = threadIdx.x;
    int jl = tid & 31, chunk = tid >> 5;
    int b = b0 + (blockIdx.x >> 7);
    int tile = blockIdx.x & 127;
    int j = tile * 64 + 2 * jl;

    float mc;
    if (first) {
        mc = GB2;                            // r == 0 on iteration 0
        rr[tid] = -GB2;
        __syncthreads();
    } else {
        float a0 = g_r[b * TT + tid];        // issue early; overlaps warp-0 fold
        if (tid < 32) {
            float m = NEG_BIG;
#pragma unroll
            for (int q = 0; q < 4; q++) m = fmaxf(m, g_rmaxb[b * 128 + tid * 4 + q]);
#pragma unroll
            for (int o = 16; o; o >>= 1) m = fmaxf(m, __shfl_xor_sync(~0u, m, o));
            if (tid == 0) mcs = m + GB2;
        }
        __syncthreads();
        mc = mcs;
        rr[tid] = a0 - mc;
        __syncthreads();
    }

    const float* gp = g + ((size_t)(b * TT) + (size_t)chunk * 32) * NN + j;
    const float* rp = rr + chunk * 32;
    float sx0 = 0.f, sy0 = 0.f, sx1 = 0.f, sy1 = 0.f;
#pragma unroll 4
    for (int i = 0; i < 32; i += 2) {
        float2 h0 = *(const float2*)(gp + (size_t)i * NN);
        float2 h1 = *(const float2*)(gp + (size_t)(i + 1) * NN);
        float r0 = rp[i], r1 = rp[i + 1];
        sx0 += ex2(fmaf(h0.x, C2, r0));
        sy0 += ex2(fmaf(h0.y, C2, r0));
        sx1 += ex2(fmaf(h1.x, C2, r1));
        sy1 += ex2(fmaf(h1.y, C2, r1));
    }
    ps[chunk][jl] = make_float2(sx0 + sx1, sy0 + sy1);
    __syncthreads();
    if (chunk < 8) {
        float tx = ps[4 * chunk][jl].x, ty = ps[4 * chunk][jl].y;
#pragma unroll
        for (int c = 1; c < 4; c++) {
            tx += ps[4 * chunk + c][jl].x;
            ty += ps[4 * chunk + c][jl].y;
        }
        ps2[chunk][jl] = make_float2(tx, ty);
    }
    __syncthreads();
    if (chunk == 0) {
        float tx = ps2[0][jl].x, ty = ps2[0][jl].y;
#pragma unroll
        for (int c = 1; c < 8; c++) { tx += ps2[c][jl].x; ty += ps2[c][jl].y; }
        float cx = -(mc + __log2f(tx));
        float cy = -(mc + __log2f(ty));
        g_v[b * NN + j]     = cx;
        g_v[b * NN + j + 1] = cy;
        // per-tile cmax handoff for k_row's Mr (removes its block reduce)
        float m = fmaxf(cx, cy);
#pragma unroll
        for (int o = 16; o; o >>= 1) m = fmaxf(m, __shfl_xor_sync(~0u, m, o));
        if (jl == 0) g_cmaxb[b * 128 + tile] = m;
    }
}

// ---- row pass, 8 rows/block (halves v-vector re-read traffic vs 4 rows),
// 1024 thr = 8 rows x 4 quarter-row warps. grid: 2 batches * 128 blocks
// (single wave: 2 blocks/SM x 148 = 296 slots >= 256).
__global__ void __launch_bounds__(1024) k_row(const float* __restrict__ g, int b0) {
    cudaGridDependencySynchronize();    // PDL: MUST precede any global read
    __shared__ float vs[NN];            // 32KB staged v (shifted by -Mr)
    __shared__ float Mrs;
    __shared__ float wsum[32];
    int tid = threadIdx.x;
    int b = b0 + (blockIdx.x >> 7);
    int blk = blockIdx.x & 127;
    int r0 = blk * 8;

    const float4* vp = (const float4*)(g_v + (size_t)b * NN);
    float4 hold0 = vp[tid];
    float4 hold1 = vp[tid + 1024];      // in flight early
    if (tid < 32) {
        float m = NEG_BIG;
#pragma unroll
        for (int q = 0; q < 4; q++) m = fmaxf(m, g_cmaxb[b * 128 + tid * 4 + q]);
#pragma unroll
        for (int o = 16; o; o >>= 1) m = fmaxf(m, __shfl_xor_sync(~0u, m, o));
        if (tid == 0) Mrs = m + GB2;
    }
    __syncthreads();
    float Mr = Mrs;
    hold0.x -= Mr; hold0.y -= Mr; hold0.z -= Mr; hold0.w -= Mr;
    hold1.x -= Mr; hold1.y -= Mr; hold1.z -= Mr; hold1.w -= Mr;
    ((float4*)vs)[tid] = hold0;
    ((float4*)vs)[tid + 1024] = hold1;
    __syncthreads();

    int w = tid >> 5, l = tid & 31;
    int row = r0 + (w >> 2), q = w & 3;
    const float4* gp = (const float4*)(g + ((size_t)(b * TT + row)) * NN + q * 2048);
    const float4* vq = (const float4*)(vs + q * 2048);
    float s0 = 0.f, s1 = 0.f, s2 = 0.f, s3 = 0.f;
#pragma unroll
    for (int k = 0; k < 16; k++) {
        float4 h = gp[l + 32 * k];
        float4 v = vq[l + 32 * k];
        s0 += ex2(fmaf(h.x, C2, v.x));
        s1 += ex2(fmaf(h.y, C2, v.y));
        s2 += ex2(fmaf(h.z, C2, v.z));
        s3 += ex2(fmaf(h.w, C2, v.w));
    }
    float s = (s0 + s1) + (s2 + s3);
#pragma unroll
    for (int o = 16; o; o >>= 1) s += __shfl_xor_sync(~0u, s, o);
    if (l == 0) wsum[w] = s;
    __syncthreads();
    float rloc = NEG_BIG;
    if (tid < 8) {
        float t = (wsum[4 * tid] + wsum[4 * tid + 1]) +
                  (wsum[4 * tid + 2] + wsum[4 * tid + 3]);
        rloc = -(Mr + __log2f(t));
        g_r[b * TT + r0 + tid] = rloc;
    }
    if (tid < 32) {
        // fold lanes 0..7 into lane 0 (others hold NEG_BIG)
        float m = rloc;
        m = fmaxf(m, __shfl_xor_sync(~0u, m, 1));
        m = fmaxf(m, __shfl_xor_sync(~0u, m, 2));
        m = fmaxf(m, __shfl_xor_sync(~0u, m, 4));
        if (tid == 0) g_rmaxb[b * 128 + blk] = m;
    }
}

// ---- final argmax, 8 rows/block, v staged in smem (log domain)
__global__ void __launch_bounds__(1024) k_argmax(const float* __restrict__ g,
                                                 float* __restrict__ out, int b0) {
    cudaGridDependencySynchronize();    // PDL: MUST precede any global read
    __shared__ float vs[NN];
    __shared__ float wv[32];
    __shared__ int   wi[32];
    int tid = threadIdx.x;
    int b = b0 + (blockIdx.x >> 7);
    int r0 = (blockIdx.x & 127) * 8;

    const float4* vp = (const float4*)(g_v + (size_t)b * NN);
    ((float4*)vs)[tid] = vp[tid];
    ((float4*)vs)[tid + 1024] = vp[tid + 1024];
    __syncthreads();

    int w = tid >> 5, l = tid & 31;
    int row = r0 + (w >> 2), q = w & 3;
    const float4* gp = (const float4*)(g + ((size_t)(b * TT + row)) * NN + q * 2048);
    const float4* vq = (const float4*)(vs + q * 2048);
    float b0v = NEG_BIG, b1v = NEG_BIG, b2v = NEG_BIG, b3v = NEG_BIG;
    int i0 = 0, i1 = 0, i2 = 0, i3 = 0;
#pragma unroll
    for (int k = 0; k < 16; k++) {
        int idx = l + 32 * k;
        float4 h = gp[idx];
        float4 v = vq[idx];
        int j0 = q * 2048 + idx * 4;
        float t0 = fmaf(h.x, C2, v.x), t1 = fmaf(h.y, C2, v.y);
        float t2 = fmaf(h.z, C2, v.z), t3 = fmaf(h.w, C2, v.w);
        if (t0 > b0v) { b0v = t0; i0 = j0; }
        if (t1 > b1v) { b1v = t1; i1 = j0 + 1; }
        if (t2 > b2v) { b2v = t2; i2 = j0 + 2; }
        if (t3 > b3v) { b3v = t3; i3 = j0 + 3; }
    }
    if (b1v > b0v || (b1v == b0v && i1 < i0)) { b0v = b1v; i0 = i1; }
    if (b3v > b2v || (b3v == b2v && i3 < i2)) { b2v = b3v; i2 = i3; }
    if (b2v > b0v || (b2v == b0v && i2 < i0)) { b0v = b2v; i0 = i2; }
#pragma unroll
    for (int o = 16; o; o >>= 1) {
        float bv = __shfl_down_sync(~0u, b0v, o);
        int   iv = __shfl_down_sync(~0u, i0, o);
        if (bv > b0v || (bv == b0v && iv < i0)) { b0v = bv; i0 = iv; }
    }
    if (l == 0) { wv[w] = b0v; wi[w] = i0; }
    __syncthreads();
    if (tid < 8) {
        float bv = wv[4 * tid]; int bi = wi[4 * tid];
#pragma unroll
        for (int c = 1; c < 4; c++) {
            float v = wv[4 * tid + c]; int id = wi[4 * tid + c];
            if (v > bv || (v == bv && id < bi)) { bv = v; bi = id; }
        }
        int o0 = b * TT + r0 + tid;
        out[o0] = 1.0f;                 // s + stopgrad(1-s) == 1.0 exactly; mask all-true
        out[BB * TT + o0] = (float)bi;  // selected index
    }
}

// Launch with programmatic stream serialization so each kernel's launch
// setup overlaps its predecessor's tail.
template <typename... Args>
static void launch_pdl(void (*fn)(Args...), dim3 grid, dim3 block, Args... args) {
    cudaLaunchConfig_t cfg = {};
    cfg.gridDim = grid;
    cfg.blockDim = block;
    cfg.stream = 0;
    cudaLaunchAttribute attr[1];
    attr[0].id = cudaLaunchAttributeProgrammaticStreamSerialization;
    attr[0].val.programmaticStreamSerializationAllowed = 1;
    cfg.attrs = attr;
    cfg.numAttrs = 1;
    cudaLaunchKernelEx(&cfg, fn, args...);
}

extern "C" void kernel_launch(void* const* d_in, const int* in_sizes, int n_in,
                              void* d_out, int out_size) {
    // x and routing_token are mathematically dead: scores cancel in the first
    // axis=-2 normalization. Only gumbel matters.
    const float* g = (const float*)d_in[2];
    float* out = (float*)d_out;

    // batch-pair sets: keep 64MB gumbel slice L2-resident across all 16 sweeps
    for (int b0 = 0; b0 < BB; b0 += 2) {
        for (int it = 0; it < 8; it++) {
            launch_pdl(k_col, dim3(256), dim3(1024), g, b0, it == 0 ? 1 : 0);
            if (it < 7) launch_pdl(k_row, dim3(256), dim3(1024), g, b0);
        }
        launch_pdl(k_argmax, dim3(256), dim3(1024), g, out, b0);
    }
}